// round 7
// baseline (speedup 1.0000x reference)
#include <cuda_runtime.h>
#include <math.h>

// ---------------------------------------------------------------------------
// QuantumNATExtendedQML — R6: conv1 restructured for occupancy (2 ocs x 4 px
// per thread, interleaved groups, ~68 regs), column-owner tile loads (no
// div/mod) in both convs. Pipeline: conv1 -> conv2 -> pool_final (3 launches).
// ---------------------------------------------------------------------------

#define NB 128

// persistent device scratch (no cudaMalloc allowed); zero-initialized.
__device__ double g_stats1[16];                            // sum[8], sumsq[8] conv1
__device__ double g_stats2[8];                             // sum[4], sumsq[4] conv2
__device__ unsigned int g_done;                            // pool-block counter
__device__ __align__(16) float g_h1max[NB * 112 * 112 * 8];// pooled raw conv1 max, ch-last
__device__ __align__(16) float g_h1min[NB * 112 * 112 * 8];// pooled raw conv1 min, ch-last
__device__ __align__(16) float g_pmax[NB * 56 * 56 * 4];   // pooled raw conv2 max, ch-last
__device__ __align__(16) float g_pmin[NB * 56 * 56 * 4];   // pooled raw conv2 min, ch-last
__device__ __align__(16) float g_feat[NB * 4];

__device__ __forceinline__ float warp_sum(float v) {
#pragma unroll
    for (int o = 16; o > 0; o >>= 1) v += __shfl_xor_sync(0xffffffffu, v, o);
    return v;
}

// ---------------------------------------------------------------------------
// Fused conv1: raw conv y -> global atomic (sum, sumsq) + 2x2 pooled raw
// max/min (ch-last).  grid(7, 128), block 224.
// grp = tid&3 -> ocs {2grp, 2grp+1};  k = tid>>2 (0..55) -> conv cols 4k..4k+3
// (pooled cols 2k, 2k+1).  Strip: 32 conv rows -> 16 pooled rows.
__global__ void __launch_bounds__(224) k_conv1(const float* __restrict__ x,
                                               const float* __restrict__ w,
                                               const float* __restrict__ bias) {
    __shared__ __align__(16) float tile[34][228];
    __shared__ double sacc[16];
    const int n = blockIdx.y, h0 = blockIdx.x * 32, tid = threadIdx.x;
    const int grp = tid & 3, k = tid >> 2, lane = tid & 31;

    if (tid < 16) sacc[tid] = 0.0;

    // column-owner tile load: thread owns tile col c, loops 34 rows (coalesced)
    const float* xim = x + (size_t)n * 224 * 224;
    for (int c = tid; c < 226; c += 224) {
        const int ww = c - 1;
        const bool cok = (ww >= 0) && (ww < 224);
#pragma unroll 2
        for (int r = 0; r < 34; r++) {
            int hh = h0 - 1 + r;
            float v = 0.f;
            if (cok && hh >= 0 && hh < 224) v = xim[hh * 224 + ww];
            tile[r][c] = v;
        }
    }

    float wr[18], br[2];
#pragma unroll
    for (int j = 0; j < 2; j++) {
        int oc = grp * 2 + j;
#pragma unroll
        for (int t = 0; t < 9; t++) wr[j * 9 + t] = w[oc * 9 + t];
        br[j] = bias[oc];
    }
    __syncthreads();

    const int c0 = 4 * k;
    float w0[6], w1[6];
    {
        float4 a0 = *(const float4*)&tile[0][c0];
        float2 b0 = *(const float2*)&tile[0][c0 + 4];
        w0[0] = a0.x; w0[1] = a0.y; w0[2] = a0.z; w0[3] = a0.w; w0[4] = b0.x; w0[5] = b0.y;
        float4 a1 = *(const float4*)&tile[1][c0];
        float2 b1 = *(const float2*)&tile[1][c0 + 4];
        w1[0] = a1.x; w1[1] = a1.y; w1[2] = a1.z; w1[3] = a1.w; w1[4] = b1.x; w1[5] = b1.y;
    }

    float s[2] = {0.f, 0.f}, q[2] = {0.f, 0.f};
    float mx[2][2], mn[2][2];
    float* pmax = &g_h1max[(((size_t)n * 112 + blockIdx.x * 16) * 112 + 2 * k) * 8 + 2 * grp];
    float* pmin = &g_h1min[(((size_t)n * 112 + blockIdx.x * 16) * 112 + 2 * k) * 8 + 2 * grp];

#pragma unroll 2
    for (int r = 0; r < 32; r++) {
        float w2v[6];
        {
            float4 a = *(const float4*)&tile[r + 2][c0];
            float2 b = *(const float2*)&tile[r + 2][c0 + 4];
            w2v[0] = a.x; w2v[1] = a.y; w2v[2] = a.z; w2v[3] = a.w; w2v[4] = b.x; w2v[5] = b.y;
        }
#pragma unroll
        for (int j = 0; j < 2; j++) {
            float z[4];
#pragma unroll
            for (int p = 0; p < 4; p++) {
                float zz = br[j];
                zz = fmaf(wr[j * 9 + 0], w0[p + 0], zz);
                zz = fmaf(wr[j * 9 + 1], w0[p + 1], zz);
                zz = fmaf(wr[j * 9 + 2], w0[p + 2], zz);
                zz = fmaf(wr[j * 9 + 3], w1[p + 0], zz);
                zz = fmaf(wr[j * 9 + 4], w1[p + 1], zz);
                zz = fmaf(wr[j * 9 + 5], w1[p + 2], zz);
                zz = fmaf(wr[j * 9 + 6], w2v[p + 0], zz);
                zz = fmaf(wr[j * 9 + 7], w2v[p + 1], zz);
                zz = fmaf(wr[j * 9 + 8], w2v[p + 2], zz);
                z[p] = zz;
            }
            s[j] += (z[0] + z[1]) + (z[2] + z[3]);
            q[j] = fmaf(z[0], z[0], fmaf(z[1], z[1], fmaf(z[2], z[2], fmaf(z[3], z[3], q[j]))));
            float h0m = fmaxf(z[0], z[1]), h1m = fmaxf(z[2], z[3]);
            float l0m = fminf(z[0], z[1]), l1m = fminf(z[2], z[3]);
            if (r & 1) {
                mx[j][0] = fmaxf(mx[j][0], h0m); mx[j][1] = fmaxf(mx[j][1], h1m);
                mn[j][0] = fminf(mn[j][0], l0m); mn[j][1] = fminf(mn[j][1], l1m);
            } else {
                mx[j][0] = h0m; mx[j][1] = h1m;
                mn[j][0] = l0m; mn[j][1] = l1m;
            }
        }
        if (r & 1) {
            *(float2*)pmax       = make_float2(mx[0][0], mx[1][0]);
            *(float2*)(pmax + 8) = make_float2(mx[0][1], mx[1][1]);
            *(float2*)pmin       = make_float2(mn[0][0], mn[1][0]);
            *(float2*)(pmin + 8) = make_float2(mn[0][1], mn[1][1]);
            pmax += 112 * 8;
            pmin += 112 * 8;
        }
#pragma unroll
        for (int i = 0; i < 6; i++) { w0[i] = w1[i]; w1[i] = w2v[i]; }
    }

    // same-group reduction: lanes with equal (tid&3) are 4 apart
#pragma unroll
    for (int j = 0; j < 2; j++) {
        float ss = s[j], qq = q[j];
#pragma unroll
        for (int o = 4; o < 32; o <<= 1) {
            ss += __shfl_xor_sync(0xffffffffu, ss, o);
            qq += __shfl_xor_sync(0xffffffffu, qq, o);
        }
        if (lane < 4) {  // lane == grp for lanes 0..3
            atomicAdd(&sacc[lane * 2 + j], (double)ss);
            atomicAdd(&sacc[8 + lane * 2 + j], (double)qq);
        }
    }
    __syncthreads();
    if (tid < 16) atomicAdd(&g_stats1[tid], sacc[tid]);
}

// ---------------------------------------------------------------------------
// conv2 (oc 0..3): per-block prologue derives bn1 affine from g_stats1;
// h reconstructed on tile load as relu(a1*sel(max,min)+c1); raw y2 stats go
// atomically to g_stats2; in-block 2x2 pooled raw max/min written out.
// grid(14, 128), block 224.
__global__ void __launch_bounds__(224) k_conv2(const float* __restrict__ w2,
                                               const float* __restrict__ b2,
                                               const float* __restrict__ bn1g,
                                               const float* __restrict__ bn1b) {
    __shared__ float tile[8][10][120];
    __shared__ float4 wq[72];
    __shared__ float4 ybuf[8][112];
    __shared__ float bsh[4], s_a1[8], s_c1[8];
    __shared__ double sacc[8];
    const int n = blockIdx.y, h0 = blockIdx.x * 8, tid = threadIdx.x;

    if (tid < 8) {
        double N = 128.0 * 224.0 * 224.0;
        double mu = g_stats1[tid] / N;
        double var = g_stats1[8 + tid] / N - mu * mu;
        double a = (double)bn1g[tid] * rsqrt(var + 1e-5);
        s_a1[tid] = (float)a;
        s_c1[tid] = (float)((double)bn1b[tid] - mu * a);
    }
    if (tid < 72)  // w2 layout [16][8][3][3]; pack oc 0..3 per (ic,k)
        wq[tid] = make_float4(w2[tid], w2[72 + tid], w2[144 + tid], w2[216 + tid]);
    if (tid < 4) bsh[tid] = b2[tid];
    if (tid < 8) sacc[tid] = 0.0;
    __syncthreads();

    float a1r[8], c1r[8];
#pragma unroll
    for (int ch = 0; ch < 8; ch++) { a1r[ch] = s_a1[ch]; c1r[ch] = s_c1[ch]; }

    // column-owner tile load: thread owns tile col c (<114), loops 10 rows
    for (int c = tid; c < 114; c += 224) {
        const int ww = c - 1;
        const bool cok = (ww >= 0) && (ww < 112);
#pragma unroll 2
        for (int r = 0; r < 10; r++) {
            int hh = h0 - 1 + r;
            float v[8];
            if (cok && hh >= 0 && hh < 112) {
                size_t base = (((size_t)n * 112 + hh) * 112 + ww) * 8;
                const float4* mx = (const float4*)&g_h1max[base];
                const float4* mn = (const float4*)&g_h1min[base];
                float4 x0 = mx[0], x1 = mx[1], n0 = mn[0], n1 = mn[1];
                float raw[8] = {a1r[0] >= 0.f ? x0.x : n0.x, a1r[1] >= 0.f ? x0.y : n0.y,
                                a1r[2] >= 0.f ? x0.z : n0.z, a1r[3] >= 0.f ? x0.w : n0.w,
                                a1r[4] >= 0.f ? x1.x : n1.x, a1r[5] >= 0.f ? x1.y : n1.y,
                                a1r[6] >= 0.f ? x1.z : n1.z, a1r[7] >= 0.f ? x1.w : n1.w};
#pragma unroll
                for (int ch = 0; ch < 8; ch++)
                    v[ch] = fmaxf(fmaf(raw[ch], a1r[ch], c1r[ch]), 0.f);
            } else {
#pragma unroll
                for (int ch = 0; ch < 8; ch++) v[ch] = 0.f;
            }
#pragma unroll
            for (int ch = 0; ch < 8; ch++) tile[ch][r][c] = v[ch];
        }
    }
    __syncthreads();

    const int r = tid / 28, g = tid % 28;
    float y[4][4];  // [oc][px]
    {
        float b0 = bsh[0], b1 = bsh[1], b2v = bsh[2], b3 = bsh[3];
#pragma unroll
        for (int p = 0; p < 4; p++) {
            y[0][p] = b0; y[1][p] = b1; y[2][p] = b2v; y[3][p] = b3;
        }
    }

#pragma unroll 1
    for (int ic = 0; ic < 8; ic++) {
#pragma unroll
        for (int kh = 0; kh < 3; kh++) {
            const float4 va = *(const float4*)&tile[ic][r + kh][4 * g];
            const float2 vb = *(const float2*)&tile[ic][r + kh][4 * g + 4];
            float t[6] = {va.x, va.y, va.z, va.w, vb.x, vb.y};
#pragma unroll
            for (int kw = 0; kw < 3; kw++) {
                float4 wv = wq[ic * 9 + kh * 3 + kw];
#pragma unroll
                for (int p = 0; p < 4; p++) {
                    float u = t[p + kw];
                    y[0][p] = fmaf(wv.x, u, y[0][p]);
                    y[1][p] = fmaf(wv.y, u, y[1][p]);
                    y[2][p] = fmaf(wv.z, u, y[2][p]);
                    y[3][p] = fmaf(wv.w, u, y[3][p]);
                }
            }
        }
    }

    // bn2 stats on raw y2
#pragma unroll
    for (int j = 0; j < 4; j++) {
        float s = (y[j][0] + y[j][1]) + (y[j][2] + y[j][3]);
        float qq = fmaf(y[j][0], y[j][0], fmaf(y[j][1], y[j][1],
                   fmaf(y[j][2], y[j][2], y[j][3] * y[j][3])));
        float ws = warp_sum(s);
        float wq = warp_sum(qq);
        if ((tid & 31) == 0) {
            atomicAdd(&sacc[j], (double)ws);
            atomicAdd(&sacc[4 + j], (double)wq);
        }
    }

    // stash y into ybuf for in-block 2x2 pooling
#pragma unroll
    for (int p = 0; p < 4; p++)
        ybuf[r][4 * g + p] = make_float4(y[0][p], y[1][p], y[2][p], y[3][p]);
    __syncthreads();

    // 224 threads = 4 pooled rows x 56 pooled cols
    {
        const int ppr = tid / 56, ppw = tid % 56;
        float4 u0 = ybuf[2 * ppr][2 * ppw];
        float4 u1 = ybuf[2 * ppr][2 * ppw + 1];
        float4 u2 = ybuf[2 * ppr + 1][2 * ppw];
        float4 u3 = ybuf[2 * ppr + 1][2 * ppw + 1];
        float4 mx, mn;
        mx.x = fmaxf(fmaxf(u0.x, u1.x), fmaxf(u2.x, u3.x));
        mx.y = fmaxf(fmaxf(u0.y, u1.y), fmaxf(u2.y, u3.y));
        mx.z = fmaxf(fmaxf(u0.z, u1.z), fmaxf(u2.z, u3.z));
        mx.w = fmaxf(fmaxf(u0.w, u1.w), fmaxf(u2.w, u3.w));
        mn.x = fminf(fminf(u0.x, u1.x), fminf(u2.x, u3.x));
        mn.y = fminf(fminf(u0.y, u1.y), fminf(u2.y, u3.y));
        mn.z = fminf(fminf(u0.z, u1.z), fminf(u2.z, u3.z));
        mn.w = fminf(fminf(u0.w, u1.w), fminf(u2.w, u3.w));
        size_t o = (((size_t)n * 56 + (blockIdx.x * 4 + ppr)) * 56 + ppw) * 4;
        *(float4*)&g_pmax[o] = mx;
        *(float4*)&g_pmin[o] = mn;
    }
    if (tid < 8) atomicAdd(&g_stats2[tid], sacc[tid]);
}

// ---------------------------------------------------------------------------
// Quantum circuit helpers.
template <int Q>
__device__ __forceinline__ void ry_gate(float2* st, float t) {
    float s, c;
    sincosf(0.5f * t, &s, &c);
    const int m = 8 >> Q;
#pragma unroll
    for (int i = 0; i < 16; i++)
        if (!(i & m)) {
            float2 a0 = st[i], a1 = st[i | m];
            st[i]     = make_float2(c * a0.x - s * a1.x, c * a0.y - s * a1.y);
            st[i | m] = make_float2(s * a0.x + c * a1.x, s * a0.y + c * a1.y);
        }
}
template <int Q>
__device__ __forceinline__ void rz_gate(float2* st, float t) {
    float s, c;
    sincosf(0.5f * t, &s, &c);
    const int m = 8 >> Q;
#pragma unroll
    for (int i = 0; i < 16; i++)
        if (!(i & m)) {
            float2 a0 = st[i], a1 = st[i | m];
            st[i]     = make_float2(c * a0.x + s * a0.y, c * a0.y - s * a0.x);
            st[i | m] = make_float2(c * a1.x - s * a1.y, c * a1.y + s * a1.x);
        }
}
template <int Q>
__device__ __forceinline__ void rx_gate(float2* st, float t) {
    float s, c;
    sincosf(0.5f * t, &s, &c);
    const int m = 8 >> Q;
#pragma unroll
    for (int i = 0; i < 16; i++)
        if (!(i & m)) {
            float2 a0 = st[i], a1 = st[i | m];
            st[i]     = make_float2(c * a0.x + s * a1.y, c * a0.y - s * a1.x);
            st[i | m] = make_float2(c * a1.x + s * a0.y, c * a1.y - s * a0.x);
        }
}
template <int C, int T>
__device__ __forceinline__ void cnot_gate(float2* st) {
    const int mc = 8 >> C, mt = 8 >> T;
#pragma unroll
    for (int i = 0; i < 16; i++)
        if ((i & mc) && !(i & mt)) {
            float2 tmp = st[i];
            st[i] = st[i | mt];
            st[i | mt] = tmp;
        }
}

// ---------------------------------------------------------------------------
// pool_mean + fused final: each block computes feat[n]; the last block to
// finish (counter) runs standardize + circuit + output BN and resets state.
// grid(128), block 256.
__global__ void k_pool_final(const float* __restrict__ bn2g,
                             const float* __restrict__ bn2b,
                             const float* __restrict__ theta,
                             const float* __restrict__ rho,
                             const float* __restrict__ ng,
                             const float* __restrict__ nb,
                             float* __restrict__ out) {
    __shared__ float s_a2[4], s_c2[4];
    __shared__ unsigned int s_last;
    const int n = blockIdx.x, tid = threadIdx.x;
    if (tid < 4) {
        double N = 128.0 * 112.0 * 112.0;
        double mu = g_stats2[tid] / N;
        double var = g_stats2[4 + tid] / N - mu * mu;
        double a = (double)bn2g[tid] * rsqrt(var + 1e-5);
        s_a2[tid] = (float)a;
        s_c2[tid] = (float)((double)bn2b[tid] - mu * a);
    }
    __syncthreads();
    const float4 av = *(const float4*)s_a2;
    const float4 cv = *(const float4*)s_c2;
    const float4* pmax = (const float4*)&g_pmax[(size_t)n * 56 * 56 * 4];
    const float4* pmin = (const float4*)&g_pmin[(size_t)n * 56 * 56 * 4];
    float4 acc = make_float4(0.f, 0.f, 0.f, 0.f);

    for (int p = tid; p < 56 * 56; p += 256) {
        float4 mx = pmax[p], mn = pmin[p];
        float vx = av.x >= 0.f ? mx.x : mn.x;
        float vy = av.y >= 0.f ? mx.y : mn.y;
        float vz = av.z >= 0.f ? mx.z : mn.z;
        float vw = av.w >= 0.f ? mx.w : mn.w;
        acc.x += fmaxf(fmaf(vx, av.x, cv.x), 0.f);
        acc.y += fmaxf(fmaf(vy, av.y, cv.y), 0.f);
        acc.z += fmaxf(fmaf(vz, av.z, cv.z), 0.f);
        acc.w += fmaxf(fmaf(vw, av.w, cv.w), 0.f);
    }
    __shared__ float4 sm[8];
    acc.x = warp_sum(acc.x); acc.y = warp_sum(acc.y);
    acc.z = warp_sum(acc.z); acc.w = warp_sum(acc.w);
    if ((tid & 31) == 0) sm[tid >> 5] = acc;
    __syncthreads();
    if (tid == 0) {
        float4 t = make_float4(0.f, 0.f, 0.f, 0.f);
#pragma unroll
        for (int i = 0; i < 8; i++) {
            t.x += sm[i].x; t.y += sm[i].y; t.z += sm[i].z; t.w += sm[i].w;
        }
        *(float4*)&g_feat[n * 4] =
            make_float4(t.x / 3136.f, t.y / 3136.f, t.z / 3136.f, t.w / 3136.f);
        __threadfence();
        s_last = atomicAdd(&g_done, 1u);
    }
    __syncthreads();
    if (s_last != NB - 1) return;   // not the last block: done
    __threadfence();                // acquire: all g_feat writes visible

    // ---- fused final phase: threads 0..127 (one per batch element) ----
    if (tid == 0) {
        g_done = 0;                 // reset for graph replay
    }
    if (tid < 16) g_stats1[tid] = 0.0;
    if (tid < 8)  g_stats2[tid] = 0.0;
    if (tid >= 128) return;         // sm_70+: barriers ignore exited threads

    float f[4];
#pragma unroll
    for (int j = 0; j < 4; j++) f[j] = g_feat[tid * 4 + j];

    __shared__ double ssum, ssq;
    if (tid == 0) { ssum = 0.0; ssq = 0.0; }
    __syncthreads();
    float lf = f[0] + f[1] + f[2] + f[3];
    float lq = f[0] * f[0] + f[1] * f[1] + f[2] * f[2] + f[3] * f[3];
    float ws = warp_sum(lf), wq = warp_sum(lq);
    if ((tid & 31) == 0) { atomicAdd(&ssum, (double)ws); atomicAdd(&ssq, (double)wq); }
    __syncthreads();
    double mean = ssum / 512.0;
    double var1 = (ssq - 512.0 * mean * mean) / 511.0;
    if (var1 < 0.0) var1 = 0.0;
    float scale = (float)(3.14159265358979323846 / (sqrt(var1) + 1e-6));
    float sc[4];
#pragma unroll
    for (int j = 0; j < 4; j++) sc[j] = (float)((double)f[j] - mean) * scale;

    float2 st[16];
#pragma unroll
    for (int i = 0; i < 16; i++) st[i] = make_float2(0.f, 0.f);
    st[0].x = 1.f;

    ry_gate<0>(st, sc[0]); ry_gate<1>(st, sc[1]); ry_gate<2>(st, sc[2]); ry_gate<3>(st, sc[3]);

    ry_gate<0>(st, theta[0]);  rz_gate<0>(st, theta[1]);  rx_gate<0>(st, theta[2]);
    ry_gate<1>(st, theta[3]);  rz_gate<1>(st, theta[4]);  rx_gate<1>(st, theta[5]);
    ry_gate<2>(st, theta[6]);  rz_gate<2>(st, theta[7]);  rx_gate<2>(st, theta[8]);
    ry_gate<3>(st, theta[9]);  rz_gate<3>(st, theta[10]); rx_gate<3>(st, theta[11]);

    cnot_gate<0, 1>(st); cnot_gate<1, 2>(st); cnot_gate<2, 3>(st);

    ry_gate<0>(st, rho[0]);  rz_gate<0>(st, rho[1]);  rx_gate<0>(st, rho[2]);
    ry_gate<1>(st, rho[3]);  rz_gate<1>(st, rho[4]);  rx_gate<1>(st, rho[5]);
    ry_gate<2>(st, rho[6]);  rz_gate<2>(st, rho[7]);  rx_gate<2>(st, rho[8]);
    ry_gate<3>(st, rho[9]);  rz_gate<3>(st, rho[10]); rx_gate<3>(st, rho[11]);

    cnot_gate<1, 0>(st); cnot_gate<2, 1>(st); cnot_gate<3, 2>(st);

    float pr[16];
#pragma unroll
    for (int i = 0; i < 16; i++) pr[i] = st[i].x * st[i].x + st[i].y * st[i].y;

    float e[4];
#pragma unroll
    for (int q = 0; q < 4; q++) {
        const int m = 8 >> q;
        float a = 0.f;
#pragma unroll
        for (int i = 0; i < 16; i++) a += (i & m) ? -pr[i] : pr[i];
        e[q] = a;
    }

    __shared__ double s1, s2;
#pragma unroll
    for (int j = 0; j < 4; j++) {
        if (tid == 0) { s1 = 0.0; s2 = 0.0; }
        __syncthreads();
        float v = e[j];
        float w1 = warp_sum(v), w2 = warp_sum(v * v);
        if ((tid & 31) == 0) { atomicAdd(&s1, (double)w1); atomicAdd(&s2, (double)w2); }
        __syncthreads();
        double mu = s1 / 128.0;
        double vv = s2 / 128.0 - mu * mu;
        out[tid * 4 + j] =
            (float)(((double)v - mu) * rsqrt(vv + 1e-5) * (double)ng[j] + (double)nb[j]);
        __syncthreads();
    }
}

// ---------------------------------------------------------------------------
extern "C" void kernel_launch(void* const* d_in, const int* in_sizes, int n_in,
                              void* d_out, int out_size) {
    const float* x     = (const float*)d_in[0];
    const float* w1    = (const float*)d_in[1];
    const float* b1    = (const float*)d_in[2];
    const float* bn1g  = (const float*)d_in[3];
    const float* bn1b  = (const float*)d_in[4];
    const float* w2    = (const float*)d_in[5];
    const float* b2    = (const float*)d_in[6];
    const float* bn2g  = (const float*)d_in[7];
    const float* bn2b  = (const float*)d_in[8];
    const float* theta = (const float*)d_in[9];
    const float* rho   = (const float*)d_in[10];
    const float* ng    = (const float*)d_in[11];
    const float* nbp   = (const float*)d_in[12];
    float* out = (float*)d_out;

    k_conv1<<<dim3(7, NB), 224>>>(x, w1, b1);
    k_conv2<<<dim3(14, NB), 224>>>(w2, b2, bn1g, bn1b);
    k_pool_final<<<NB, 256>>>(bn2g, bn2b, theta, rho, ng, nbp, out);
}

// round 8
// speedup vs baseline: 1.1581x; 1.1581x over previous
#include <cuda_runtime.h>
#include <cuda_fp16.h>
#include <math.h>

// ---------------------------------------------------------------------------
// QuantumNATExtendedQML — R7: h1 max/min intermediates stored as fp16
// (halves conv1 store + conv2 load traffic), conv1 split into 16-row strips
// (2x blocks, ~98% theoretical occupancy). Pipeline unchanged: conv1 ->
// conv2 -> pool_final (3 launches).
// ---------------------------------------------------------------------------

#define NB 128

// persistent device scratch (no cudaMalloc allowed); zero-initialized.
__device__ double g_stats1[16];                            // sum[8], sumsq[8] conv1
__device__ double g_stats2[8];                             // sum[4], sumsq[4] conv2
__device__ unsigned int g_done;                            // pool-block counter
__device__ __align__(16) __half g_h1max[NB * 112 * 112 * 8]; // pooled raw conv1 max (fp16)
__device__ __align__(16) __half g_h1min[NB * 112 * 112 * 8]; // pooled raw conv1 min (fp16)
__device__ __align__(16) float g_pmax[NB * 56 * 56 * 4];   // pooled raw conv2 max, ch-last
__device__ __align__(16) float g_pmin[NB * 56 * 56 * 4];   // pooled raw conv2 min, ch-last
__device__ __align__(16) float g_feat[NB * 4];

__device__ __forceinline__ float warp_sum(float v) {
#pragma unroll
    for (int o = 16; o > 0; o >>= 1) v += __shfl_xor_sync(0xffffffffu, v, o);
    return v;
}

// ---------------------------------------------------------------------------
// Fused conv1: raw conv y -> global atomic (sum, sumsq) + 2x2 pooled raw
// max/min (fp16, ch-last).  grid(14, 128), block 224.
// grp = tid&3 -> ocs {2grp, 2grp+1};  k = tid>>2 (0..55) -> conv cols 4k..4k+3
// (pooled cols 2k, 2k+1).  Strip: 16 conv rows -> 8 pooled rows.
__global__ void __launch_bounds__(224) k_conv1(const float* __restrict__ x,
                                               const float* __restrict__ w,
                                               const float* __restrict__ bias) {
    __shared__ __align__(16) float tile[18][228];
    __shared__ double sacc[16];
    const int n = blockIdx.y, h0 = blockIdx.x * 16, tid = threadIdx.x;
    const int grp = tid & 3, k = tid >> 2, lane = tid & 31;

    if (tid < 16) sacc[tid] = 0.0;

    // column-owner tile load: thread owns tile col c, loops 18 rows (coalesced)
    const float* xim = x + (size_t)n * 224 * 224;
    for (int c = tid; c < 226; c += 224) {
        const int ww = c - 1;
        const bool cok = (ww >= 0) && (ww < 224);
#pragma unroll 2
        for (int r = 0; r < 18; r++) {
            int hh = h0 - 1 + r;
            float v = 0.f;
            if (cok && hh >= 0 && hh < 224) v = xim[hh * 224 + ww];
            tile[r][c] = v;
        }
    }

    float wr[18], br[2];
#pragma unroll
    for (int j = 0; j < 2; j++) {
        int oc = grp * 2 + j;
#pragma unroll
        for (int t = 0; t < 9; t++) wr[j * 9 + t] = w[oc * 9 + t];
        br[j] = bias[oc];
    }
    __syncthreads();

    const int c0 = 4 * k;
    float w0[6], w1[6];
    {
        float4 a0 = *(const float4*)&tile[0][c0];
        float2 b0 = *(const float2*)&tile[0][c0 + 4];
        w0[0] = a0.x; w0[1] = a0.y; w0[2] = a0.z; w0[3] = a0.w; w0[4] = b0.x; w0[5] = b0.y;
        float4 a1 = *(const float4*)&tile[1][c0];
        float2 b1 = *(const float2*)&tile[1][c0 + 4];
        w1[0] = a1.x; w1[1] = a1.y; w1[2] = a1.z; w1[3] = a1.w; w1[4] = b1.x; w1[5] = b1.y;
    }

    float s[2] = {0.f, 0.f}, q[2] = {0.f, 0.f};
    float mx[2][2], mn[2][2];
    __half* pmax = &g_h1max[(((size_t)n * 112 + blockIdx.x * 8) * 112 + 2 * k) * 8 + 2 * grp];
    __half* pmin = &g_h1min[(((size_t)n * 112 + blockIdx.x * 8) * 112 + 2 * k) * 8 + 2 * grp];

#pragma unroll 2
    for (int r = 0; r < 16; r++) {
        float w2v[6];
        {
            float4 a = *(const float4*)&tile[r + 2][c0];
            float2 b = *(const float2*)&tile[r + 2][c0 + 4];
            w2v[0] = a.x; w2v[1] = a.y; w2v[2] = a.z; w2v[3] = a.w; w2v[4] = b.x; w2v[5] = b.y;
        }
#pragma unroll
        for (int j = 0; j < 2; j++) {
            float z[4];
#pragma unroll
            for (int p = 0; p < 4; p++) {
                float zz = br[j];
                zz = fmaf(wr[j * 9 + 0], w0[p + 0], zz);
                zz = fmaf(wr[j * 9 + 1], w0[p + 1], zz);
                zz = fmaf(wr[j * 9 + 2], w0[p + 2], zz);
                zz = fmaf(wr[j * 9 + 3], w1[p + 0], zz);
                zz = fmaf(wr[j * 9 + 4], w1[p + 1], zz);
                zz = fmaf(wr[j * 9 + 5], w1[p + 2], zz);
                zz = fmaf(wr[j * 9 + 6], w2v[p + 0], zz);
                zz = fmaf(wr[j * 9 + 7], w2v[p + 1], zz);
                zz = fmaf(wr[j * 9 + 8], w2v[p + 2], zz);
                z[p] = zz;
            }
            s[j] += (z[0] + z[1]) + (z[2] + z[3]);
            q[j] = fmaf(z[0], z[0], fmaf(z[1], z[1], fmaf(z[2], z[2], fmaf(z[3], z[3], q[j]))));
            float h0m = fmaxf(z[0], z[1]), h1m = fmaxf(z[2], z[3]);
            float l0m = fminf(z[0], z[1]), l1m = fminf(z[2], z[3]);
            if (r & 1) {
                mx[j][0] = fmaxf(mx[j][0], h0m); mx[j][1] = fmaxf(mx[j][1], h1m);
                mn[j][0] = fminf(mn[j][0], l0m); mn[j][1] = fminf(mn[j][1], l1m);
            } else {
                mx[j][0] = h0m; mx[j][1] = h1m;
                mn[j][0] = l0m; mn[j][1] = l1m;
            }
        }
        if (r & 1) {
            *(__half2*)pmax       = __halves2half2(__float2half_rn(mx[0][0]), __float2half_rn(mx[1][0]));
            *(__half2*)(pmax + 8) = __halves2half2(__float2half_rn(mx[0][1]), __float2half_rn(mx[1][1]));
            *(__half2*)pmin       = __halves2half2(__float2half_rn(mn[0][0]), __float2half_rn(mn[1][0]));
            *(__half2*)(pmin + 8) = __halves2half2(__float2half_rn(mn[0][1]), __float2half_rn(mn[1][1]));
            pmax += 112 * 8;
            pmin += 112 * 8;
        }
#pragma unroll
        for (int i = 0; i < 6; i++) { w0[i] = w1[i]; w1[i] = w2v[i]; }
    }

    // same-group reduction: lanes with equal (tid&3) are 4 apart
#pragma unroll
    for (int j = 0; j < 2; j++) {
        float ss = s[j], qq = q[j];
#pragma unroll
        for (int o = 4; o < 32; o <<= 1) {
            ss += __shfl_xor_sync(0xffffffffu, ss, o);
            qq += __shfl_xor_sync(0xffffffffu, qq, o);
        }
        if (lane < 4) {  // lane == grp for lanes 0..3
            atomicAdd(&sacc[lane * 2 + j], (double)ss);
            atomicAdd(&sacc[8 + lane * 2 + j], (double)qq);
        }
    }
    __syncthreads();
    if (tid < 16) atomicAdd(&g_stats1[tid], sacc[tid]);
}

// ---------------------------------------------------------------------------
// conv2 (oc 0..3): per-block prologue derives bn1 affine from g_stats1;
// h reconstructed on tile load (fp16 max/min -> fp32, sel by sign, affine,
// relu); raw y2 stats -> g_stats2 atomics; in-block 2x2 pooled raw max/min.
// grid(14, 128), block 224.
__global__ void __launch_bounds__(224) k_conv2(const float* __restrict__ w2,
                                               const float* __restrict__ b2,
                                               const float* __restrict__ bn1g,
                                               const float* __restrict__ bn1b) {
    __shared__ float tile[8][10][120];
    __shared__ float4 wq[72];
    __shared__ float4 ybuf[8][112];
    __shared__ float bsh[4], s_a1[8], s_c1[8];
    __shared__ double sacc[8];
    const int n = blockIdx.y, h0 = blockIdx.x * 8, tid = threadIdx.x;

    if (tid < 8) {
        double N = 128.0 * 224.0 * 224.0;
        double mu = g_stats1[tid] / N;
        double var = g_stats1[8 + tid] / N - mu * mu;
        double a = (double)bn1g[tid] * rsqrt(var + 1e-5);
        s_a1[tid] = (float)a;
        s_c1[tid] = (float)((double)bn1b[tid] - mu * a);
    }
    if (tid < 72)  // w2 layout [16][8][3][3]; pack oc 0..3 per (ic,k)
        wq[tid] = make_float4(w2[tid], w2[72 + tid], w2[144 + tid], w2[216 + tid]);
    if (tid < 4) bsh[tid] = b2[tid];
    if (tid < 8) sacc[tid] = 0.0;
    __syncthreads();

    float a1r[8], c1r[8];
#pragma unroll
    for (int ch = 0; ch < 8; ch++) { a1r[ch] = s_a1[ch]; c1r[ch] = s_c1[ch]; }

    // column-owner tile load: thread owns tile col c (<114), loops 10 rows
    for (int c = tid; c < 114; c += 224) {
        const int ww = c - 1;
        const bool cok = (ww >= 0) && (ww < 112);
#pragma unroll 2
        for (int r = 0; r < 10; r++) {
            int hh = h0 - 1 + r;
            float v[8];
            if (cok && hh >= 0 && hh < 112) {
                size_t base = (((size_t)n * 112 + hh) * 112 + ww) * 8;
                uint4 mxu = *(const uint4*)&g_h1max[base];
                uint4 mnu = *(const uint4*)&g_h1min[base];
                const __half2* mh = (const __half2*)&mxu;
                const __half2* nh = (const __half2*)&mnu;
                float mxf[8], mnf[8];
#pragma unroll
                for (int t = 0; t < 4; t++) {
                    float2 a = __half22float2(mh[t]);
                    float2 b = __half22float2(nh[t]);
                    mxf[2 * t] = a.x; mxf[2 * t + 1] = a.y;
                    mnf[2 * t] = b.x; mnf[2 * t + 1] = b.y;
                }
#pragma unroll
                for (int ch = 0; ch < 8; ch++) {
                    float raw = a1r[ch] >= 0.f ? mxf[ch] : mnf[ch];
                    v[ch] = fmaxf(fmaf(raw, a1r[ch], c1r[ch]), 0.f);
                }
            } else {
#pragma unroll
                for (int ch = 0; ch < 8; ch++) v[ch] = 0.f;
            }
#pragma unroll
            for (int ch = 0; ch < 8; ch++) tile[ch][r][c] = v[ch];
        }
    }
    __syncthreads();

    const int r = tid / 28, g = tid % 28;
    float y[4][4];  // [oc][px]
    {
        float b0 = bsh[0], b1 = bsh[1], b2v = bsh[2], b3 = bsh[3];
#pragma unroll
        for (int p = 0; p < 4; p++) {
            y[0][p] = b0; y[1][p] = b1; y[2][p] = b2v; y[3][p] = b3;
        }
    }

#pragma unroll 1
    for (int ic = 0; ic < 8; ic++) {
#pragma unroll
        for (int kh = 0; kh < 3; kh++) {
            const float4 va = *(const float4*)&tile[ic][r + kh][4 * g];
            const float2 vb = *(const float2*)&tile[ic][r + kh][4 * g + 4];
            float t[6] = {va.x, va.y, va.z, va.w, vb.x, vb.y};
#pragma unroll
            for (int kw = 0; kw < 3; kw++) {
                float4 wv = wq[ic * 9 + kh * 3 + kw];
#pragma unroll
                for (int p = 0; p < 4; p++) {
                    float u = t[p + kw];
                    y[0][p] = fmaf(wv.x, u, y[0][p]);
                    y[1][p] = fmaf(wv.y, u, y[1][p]);
                    y[2][p] = fmaf(wv.z, u, y[2][p]);
                    y[3][p] = fmaf(wv.w, u, y[3][p]);
                }
            }
        }
    }

    // bn2 stats on raw y2
#pragma unroll
    for (int j = 0; j < 4; j++) {
        float s = (y[j][0] + y[j][1]) + (y[j][2] + y[j][3]);
        float qq = fmaf(y[j][0], y[j][0], fmaf(y[j][1], y[j][1],
                   fmaf(y[j][2], y[j][2], y[j][3] * y[j][3])));
        float ws = warp_sum(s);
        float wq = warp_sum(qq);
        if ((tid & 31) == 0) {
            atomicAdd(&sacc[j], (double)ws);
            atomicAdd(&sacc[4 + j], (double)wq);
        }
    }

    // stash y into ybuf for in-block 2x2 pooling
#pragma unroll
    for (int p = 0; p < 4; p++)
        ybuf[r][4 * g + p] = make_float4(y[0][p], y[1][p], y[2][p], y[3][p]);
    __syncthreads();

    // 224 threads = 4 pooled rows x 56 pooled cols
    {
        const int ppr = tid / 56, ppw = tid % 56;
        float4 u0 = ybuf[2 * ppr][2 * ppw];
        float4 u1 = ybuf[2 * ppr][2 * ppw + 1];
        float4 u2 = ybuf[2 * ppr + 1][2 * ppw];
        float4 u3 = ybuf[2 * ppr + 1][2 * ppw + 1];
        float4 mx, mn;
        mx.x = fmaxf(fmaxf(u0.x, u1.x), fmaxf(u2.x, u3.x));
        mx.y = fmaxf(fmaxf(u0.y, u1.y), fmaxf(u2.y, u3.y));
        mx.z = fmaxf(fmaxf(u0.z, u1.z), fmaxf(u2.z, u3.z));
        mx.w = fmaxf(fmaxf(u0.w, u1.w), fmaxf(u2.w, u3.w));
        mn.x = fminf(fminf(u0.x, u1.x), fminf(u2.x, u3.x));
        mn.y = fminf(fminf(u0.y, u1.y), fminf(u2.y, u3.y));
        mn.z = fminf(fminf(u0.z, u1.z), fminf(u2.z, u3.z));
        mn.w = fminf(fminf(u0.w, u1.w), fminf(u2.w, u3.w));
        size_t o = (((size_t)n * 56 + (blockIdx.x * 4 + ppr)) * 56 + ppw) * 4;
        *(float4*)&g_pmax[o] = mx;
        *(float4*)&g_pmin[o] = mn;
    }
    if (tid < 8) atomicAdd(&g_stats2[tid], sacc[tid]);
}

// ---------------------------------------------------------------------------
// Quantum circuit helpers.
template <int Q>
__device__ __forceinline__ void ry_gate(float2* st, float t) {
    float s, c;
    sincosf(0.5f * t, &s, &c);
    const int m = 8 >> Q;
#pragma unroll
    for (int i = 0; i < 16; i++)
        if (!(i & m)) {
            float2 a0 = st[i], a1 = st[i | m];
            st[i]     = make_float2(c * a0.x - s * a1.x, c * a0.y - s * a1.y);
            st[i | m] = make_float2(s * a0.x + c * a1.x, s * a0.y + c * a1.y);
        }
}
template <int Q>
__device__ __forceinline__ void rz_gate(float2* st, float t) {
    float s, c;
    sincosf(0.5f * t, &s, &c);
    const int m = 8 >> Q;
#pragma unroll
    for (int i = 0; i < 16; i++)
        if (!(i & m)) {
            float2 a0 = st[i], a1 = st[i | m];
            st[i]     = make_float2(c * a0.x + s * a0.y, c * a0.y - s * a0.x);
            st[i | m] = make_float2(c * a1.x - s * a1.y, c * a1.y + s * a1.x);
        }
}
template <int Q>
__device__ __forceinline__ void rx_gate(float2* st, float t) {
    float s, c;
    sincosf(0.5f * t, &s, &c);
    const int m = 8 >> Q;
#pragma unroll
    for (int i = 0; i < 16; i++)
        if (!(i & m)) {
            float2 a0 = st[i], a1 = st[i | m];
            st[i]     = make_float2(c * a0.x + s * a1.y, c * a0.y - s * a1.x);
            st[i | m] = make_float2(c * a1.x + s * a0.y, c * a1.y - s * a0.x);
        }
}
template <int C, int T>
__device__ __forceinline__ void cnot_gate(float2* st) {
    const int mc = 8 >> C, mt = 8 >> T;
#pragma unroll
    for (int i = 0; i < 16; i++)
        if ((i & mc) && !(i & mt)) {
            float2 tmp = st[i];
            st[i] = st[i | mt];
            st[i | mt] = tmp;
        }
}

// ---------------------------------------------------------------------------
// pool_mean + fused final: each block computes feat[n]; the last block to
// finish (counter) runs standardize + circuit + output BN and resets state.
// grid(128), block 256.
__global__ void k_pool_final(const float* __restrict__ bn2g,
                             const float* __restrict__ bn2b,
                             const float* __restrict__ theta,
                             const float* __restrict__ rho,
                             const float* __restrict__ ng,
                             const float* __restrict__ nb,
                             float* __restrict__ out) {
    __shared__ float s_a2[4], s_c2[4];
    __shared__ unsigned int s_last;
    const int n = blockIdx.x, tid = threadIdx.x;
    if (tid < 4) {
        double N = 128.0 * 112.0 * 112.0;
        double mu = g_stats2[tid] / N;
        double var = g_stats2[4 + tid] / N - mu * mu;
        double a = (double)bn2g[tid] * rsqrt(var + 1e-5);
        s_a2[tid] = (float)a;
        s_c2[tid] = (float)((double)bn2b[tid] - mu * a);
    }
    __syncthreads();
    const float4 av = *(const float4*)s_a2;
    const float4 cv = *(const float4*)s_c2;
    const float4* pmax = (const float4*)&g_pmax[(size_t)n * 56 * 56 * 4];
    const float4* pmin = (const float4*)&g_pmin[(size_t)n * 56 * 56 * 4];
    float4 acc = make_float4(0.f, 0.f, 0.f, 0.f);

    for (int p = tid; p < 56 * 56; p += 256) {
        float4 mx = pmax[p], mn = pmin[p];
        float vx = av.x >= 0.f ? mx.x : mn.x;
        float vy = av.y >= 0.f ? mx.y : mn.y;
        float vz = av.z >= 0.f ? mx.z : mn.z;
        float vw = av.w >= 0.f ? mx.w : mn.w;
        acc.x += fmaxf(fmaf(vx, av.x, cv.x), 0.f);
        acc.y += fmaxf(fmaf(vy, av.y, cv.y), 0.f);
        acc.z += fmaxf(fmaf(vz, av.z, cv.z), 0.f);
        acc.w += fmaxf(fmaf(vw, av.w, cv.w), 0.f);
    }
    __shared__ float4 sm[8];
    acc.x = warp_sum(acc.x); acc.y = warp_sum(acc.y);
    acc.z = warp_sum(acc.z); acc.w = warp_sum(acc.w);
    if ((tid & 31) == 0) sm[tid >> 5] = acc;
    __syncthreads();
    if (tid == 0) {
        float4 t = make_float4(0.f, 0.f, 0.f, 0.f);
#pragma unroll
        for (int i = 0; i < 8; i++) {
            t.x += sm[i].x; t.y += sm[i].y; t.z += sm[i].z; t.w += sm[i].w;
        }
        *(float4*)&g_feat[n * 4] =
            make_float4(t.x / 3136.f, t.y / 3136.f, t.z / 3136.f, t.w / 3136.f);
        __threadfence();
        s_last = atomicAdd(&g_done, 1u);
    }
    __syncthreads();
    if (s_last != NB - 1) return;   // not the last block: done
    __threadfence();                // acquire: all g_feat writes visible

    // ---- fused final phase: threads 0..127 (one per batch element) ----
    if (tid == 0) {
        g_done = 0;                 // reset for graph replay
    }
    if (tid < 16) g_stats1[tid] = 0.0;
    if (tid < 8)  g_stats2[tid] = 0.0;
    if (tid >= 128) return;         // sm_70+: barriers ignore exited threads

    float f[4];
#pragma unroll
    for (int j = 0; j < 4; j++) f[j] = g_feat[tid * 4 + j];

    __shared__ double ssum, ssq;
    if (tid == 0) { ssum = 0.0; ssq = 0.0; }
    __syncthreads();
    float lf = f[0] + f[1] + f[2] + f[3];
    float lq = f[0] * f[0] + f[1] * f[1] + f[2] * f[2] + f[3] * f[3];
    float ws = warp_sum(lf), wq = warp_sum(lq);
    if ((tid & 31) == 0) { atomicAdd(&ssum, (double)ws); atomicAdd(&ssq, (double)wq); }
    __syncthreads();
    double mean = ssum / 512.0;
    double var1 = (ssq - 512.0 * mean * mean) / 511.0;
    if (var1 < 0.0) var1 = 0.0;
    float scale = (float)(3.14159265358979323846 / (sqrt(var1) + 1e-6));
    float sc[4];
#pragma unroll
    for (int j = 0; j < 4; j++) sc[j] = (float)((double)f[j] - mean) * scale;

    float2 st[16];
#pragma unroll
    for (int i = 0; i < 16; i++) st[i] = make_float2(0.f, 0.f);
    st[0].x = 1.f;

    ry_gate<0>(st, sc[0]); ry_gate<1>(st, sc[1]); ry_gate<2>(st, sc[2]); ry_gate<3>(st, sc[3]);

    ry_gate<0>(st, theta[0]);  rz_gate<0>(st, theta[1]);  rx_gate<0>(st, theta[2]);
    ry_gate<1>(st, theta[3]);  rz_gate<1>(st, theta[4]);  rx_gate<1>(st, theta[5]);
    ry_gate<2>(st, theta[6]);  rz_gate<2>(st, theta[7]);  rx_gate<2>(st, theta[8]);
    ry_gate<3>(st, theta[9]);  rz_gate<3>(st, theta[10]); rx_gate<3>(st, theta[11]);

    cnot_gate<0, 1>(st); cnot_gate<1, 2>(st); cnot_gate<2, 3>(st);

    ry_gate<0>(st, rho[0]);  rz_gate<0>(st, rho[1]);  rx_gate<0>(st, rho[2]);
    ry_gate<1>(st, rho[3]);  rz_gate<1>(st, rho[4]);  rx_gate<1>(st, rho[5]);
    ry_gate<2>(st, rho[6]);  rz_gate<2>(st, rho[7]);  rx_gate<2>(st, rho[8]);
    ry_gate<3>(st, rho[9]);  rz_gate<3>(st, rho[10]); rx_gate<3>(st, rho[11]);

    cnot_gate<1, 0>(st); cnot_gate<2, 1>(st); cnot_gate<3, 2>(st);

    float pr[16];
#pragma unroll
    for (int i = 0; i < 16; i++) pr[i] = st[i].x * st[i].x + st[i].y * st[i].y;

    float e[4];
#pragma unroll
    for (int q = 0; q < 4; q++) {
        const int m = 8 >> q;
        float a = 0.f;
#pragma unroll
        for (int i = 0; i < 16; i++) a += (i & m) ? -pr[i] : pr[i];
        e[q] = a;
    }

    __shared__ double s1, s2;
#pragma unroll
    for (int j = 0; j < 4; j++) {
        if (tid == 0) { s1 = 0.0; s2 = 0.0; }
        __syncthreads();
        float v = e[j];
        float w1 = warp_sum(v), w2 = warp_sum(v * v);
        if ((tid & 31) == 0) { atomicAdd(&s1, (double)w1); atomicAdd(&s2, (double)w2); }
        __syncthreads();
        double mu = s1 / 128.0;
        double vv = s2 / 128.0 - mu * mu;
        out[tid * 4 + j] =
            (float)(((double)v - mu) * rsqrt(vv + 1e-5) * (double)ng[j] + (double)nb[j]);
        __syncthreads();
    }
}

// ---------------------------------------------------------------------------
extern "C" void kernel_launch(void* const* d_in, const int* in_sizes, int n_in,
                              void* d_out, int out_size) {
    const float* x     = (const float*)d_in[0];
    const float* w1    = (const float*)d_in[1];
    const float* b1    = (const float*)d_in[2];
    const float* bn1g  = (const float*)d_in[3];
    const float* bn1b  = (const float*)d_in[4];
    const float* w2    = (const float*)d_in[5];
    const float* b2    = (const float*)d_in[6];
    const float* bn2g  = (const float*)d_in[7];
    const float* bn2b  = (const float*)d_in[8];
    const float* theta = (const float*)d_in[9];
    const float* rho   = (const float*)d_in[10];
    const float* ng    = (const float*)d_in[11];
    const float* nbp   = (const float*)d_in[12];
    float* out = (float*)d_out;

    k_conv1<<<dim3(14, NB), 224>>>(x, w1, b1);
    k_conv2<<<dim3(14, NB), 224>>>(w2, b2, bn1g, bn1b);
    k_pool_final<<<NB, 256>>>(bn2g, bn2b, theta, rho, ng, nbp, out);
}

// round 9
// speedup vs baseline: 1.2488x; 1.0783x over previous
#include <cuda_runtime.h>
#include <math.h>

// ---------------------------------------------------------------------------
// QuantumNATExtendedQML — R8: sign-folded single-plane intermediates.
// sign(a_bn) == sign(gamma) is known at launch, so conv1 folds s=sign(g) into
// its weights (min(z) = -max(-z)) and stores ONE fp32 plane holding exactly
// the extremum the next stage needs. Same DRAM bytes as the fp16 dual-plane
// scheme, full fp32 accuracy. Same trick for conv2 -> pooled plane.
// Pipeline: conv1 -> conv2 -> pool_final (3 launches).
// ---------------------------------------------------------------------------

#define NB 128

// persistent device scratch (no cudaMalloc allowed); zero-initialized.
__device__ double g_stats1[16];                            // sum[8], sumsq[8] conv1 (true z)
__device__ double g_stats2[8];                             // sum[4], sumsq[4] conv2 (true y)
__device__ unsigned int g_done;                            // pool-block counter
__device__ __align__(16) float g_h1[NB * 112 * 112 * 8];   // pooled extremum of s1*z, ch-last
__device__ __align__(16) float g_p2[NB * 56 * 56 * 4];     // pooled extremum of s2*y, ch-last
__device__ __align__(16) float g_feat[NB * 4];

__device__ __forceinline__ float warp_sum(float v) {
#pragma unroll
    for (int o = 16; o > 0; o >>= 1) v += __shfl_xor_sync(0xffffffffu, v, o);
    return v;
}

// ---------------------------------------------------------------------------
// Fused conv1: z' = s*conv(x) (s = sign(bn1g) folded into w,b) -> global
// atomic true (sum, sumsq) + 2x2 pooled max(z') (fp32, ch-last).
// grid(14, 128), block 224.  grp = tid&3 -> ocs {2grp, 2grp+1};
// k = tid>>2 -> conv cols 4k..4k+3 (pooled 2k, 2k+1).  16 conv rows/strip.
__global__ void __launch_bounds__(224) k_conv1(const float* __restrict__ x,
                                               const float* __restrict__ w,
                                               const float* __restrict__ bias,
                                               const float* __restrict__ bn1g) {
    __shared__ __align__(16) float tile[18][228];
    __shared__ double sacc[16];
    const int n = blockIdx.y, h0 = blockIdx.x * 16, tid = threadIdx.x;
    const int grp = tid & 3, k = tid >> 2, lane = tid & 31;

    if (tid < 16) sacc[tid] = 0.0;

    // column-owner tile load: thread owns tile col c, loops 18 rows
    const float* xim = x + (size_t)n * 224 * 224;
    for (int c = tid; c < 226; c += 224) {
        const int ww = c - 1;
        const bool cok = (ww >= 0) && (ww < 224);
#pragma unroll 2
        for (int r = 0; r < 18; r++) {
            int hh = h0 - 1 + r;
            float v = 0.f;
            if (cok && hh >= 0 && hh < 224) v = xim[hh * 224 + ww];
            tile[r][c] = v;
        }
    }

    float wr[18], br[2], sg[2];
#pragma unroll
    for (int j = 0; j < 2; j++) {
        int oc = grp * 2 + j;
        float s = (bn1g[oc] >= 0.f) ? 1.f : -1.f;
        sg[j] = s;
#pragma unroll
        for (int t = 0; t < 9; t++) wr[j * 9 + t] = w[oc * 9 + t] * s;
        br[j] = bias[oc] * s;
    }
    __syncthreads();

    const int c0 = 4 * k;
    float w0[6], w1[6];
    {
        float4 a0 = *(const float4*)&tile[0][c0];
        float2 b0 = *(const float2*)&tile[0][c0 + 4];
        w0[0] = a0.x; w0[1] = a0.y; w0[2] = a0.z; w0[3] = a0.w; w0[4] = b0.x; w0[5] = b0.y;
        float4 a1 = *(const float4*)&tile[1][c0];
        float2 b1 = *(const float2*)&tile[1][c0 + 4];
        w1[0] = a1.x; w1[1] = a1.y; w1[2] = a1.z; w1[3] = a1.w; w1[4] = b1.x; w1[5] = b1.y;
    }

    float s[2] = {0.f, 0.f}, q[2] = {0.f, 0.f};
    float mx[2][2];
    float* psel = &g_h1[(((size_t)n * 112 + blockIdx.x * 8) * 112 + 2 * k) * 8 + 2 * grp];

#pragma unroll 2
    for (int r = 0; r < 16; r++) {
        float w2v[6];
        {
            float4 a = *(const float4*)&tile[r + 2][c0];
            float2 b = *(const float2*)&tile[r + 2][c0 + 4];
            w2v[0] = a.x; w2v[1] = a.y; w2v[2] = a.z; w2v[3] = a.w; w2v[4] = b.x; w2v[5] = b.y;
        }
#pragma unroll
        for (int j = 0; j < 2; j++) {
            float z[4];
#pragma unroll
            for (int p = 0; p < 4; p++) {
                float zz = br[j];
                zz = fmaf(wr[j * 9 + 0], w0[p + 0], zz);
                zz = fmaf(wr[j * 9 + 1], w0[p + 1], zz);
                zz = fmaf(wr[j * 9 + 2], w0[p + 2], zz);
                zz = fmaf(wr[j * 9 + 3], w1[p + 0], zz);
                zz = fmaf(wr[j * 9 + 4], w1[p + 1], zz);
                zz = fmaf(wr[j * 9 + 5], w1[p + 2], zz);
                zz = fmaf(wr[j * 9 + 6], w2v[p + 0], zz);
                zz = fmaf(wr[j * 9 + 7], w2v[p + 1], zz);
                zz = fmaf(wr[j * 9 + 8], w2v[p + 2], zz);
                z[p] = zz;
            }
            s[j] += (z[0] + z[1]) + (z[2] + z[3]);
            q[j] = fmaf(z[0], z[0], fmaf(z[1], z[1], fmaf(z[2], z[2], fmaf(z[3], z[3], q[j]))));
            float h0m = fmaxf(z[0], z[1]), h1m = fmaxf(z[2], z[3]);
            if (r & 1) {
                mx[j][0] = fmaxf(mx[j][0], h0m);
                mx[j][1] = fmaxf(mx[j][1], h1m);
            } else {
                mx[j][0] = h0m;
                mx[j][1] = h1m;
            }
        }
        if (r & 1) {
            *(float2*)psel       = make_float2(mx[0][0], mx[1][0]);
            *(float2*)(psel + 8) = make_float2(mx[0][1], mx[1][1]);
            psel += 112 * 8;
        }
#pragma unroll
        for (int i = 0; i < 6; i++) { w0[i] = w1[i]; w1[i] = w2v[i]; }
    }

    // same-group reduction: lanes with equal (tid&3) are 4 apart.
    // sum was accumulated on z' = s*z; re-sign to get the true sum.
#pragma unroll
    for (int j = 0; j < 2; j++) {
        float ss = s[j], qq = q[j];
#pragma unroll
        for (int o = 4; o < 32; o <<= 1) {
            ss += __shfl_xor_sync(0xffffffffu, ss, o);
            qq += __shfl_xor_sync(0xffffffffu, qq, o);
        }
        if (lane < 4) {  // lane == grp for lanes 0..3
            atomicAdd(&sacc[lane * 2 + j], (double)(ss * sg[j]));
            atomicAdd(&sacc[8 + lane * 2 + j], (double)qq);
        }
    }
    __syncthreads();
    if (tid < 16) atomicAdd(&g_stats1[tid], sacc[tid]);
}

// ---------------------------------------------------------------------------
// conv2 (oc 0..3): prologue derives bn1 affine from g_stats1; tile load does
// h = relu(|a1|*stored + c1) (stored plane already holds the right extremum).
// s2 = sign(bn2g) folded into w2,b2; raw-y stats re-signed to g_stats2;
// in-block 2x2 pooled max(y') written as single plane.  grid(14,128), blk 224.
__global__ void __launch_bounds__(224) k_conv2(const float* __restrict__ w2,
                                               const float* __restrict__ b2,
                                               const float* __restrict__ bn1g,
                                               const float* __restrict__ bn1b,
                                               const float* __restrict__ bn2g) {
    __shared__ float tile[8][10][120];
    __shared__ float4 wq[72];
    __shared__ float4 ybuf[8][112];
    __shared__ float bsh[4], s_s2[4], s_a1[8], s_c1[8];
    __shared__ double sacc[8];
    const int n = blockIdx.y, h0 = blockIdx.x * 8, tid = threadIdx.x;

    if (tid < 8) {
        double N = 128.0 * 224.0 * 224.0;
        double mu = g_stats1[tid] / N;
        double var = g_stats1[8 + tid] / N - mu * mu;
        double a = (double)bn1g[tid] * rsqrt(var + 1e-5);
        s_a1[tid] = fabsf((float)a);                       // used with stored plane
        s_c1[tid] = (float)((double)bn1b[tid] - mu * a);
    }
    if (tid < 72) {  // w2 layout [16][8][3][3]; pack oc 0..3, fold s2
        float sg0 = bn2g[0] >= 0.f ? 1.f : -1.f;
        float sg1 = bn2g[1] >= 0.f ? 1.f : -1.f;
        float sg2 = bn2g[2] >= 0.f ? 1.f : -1.f;
        float sg3 = bn2g[3] >= 0.f ? 1.f : -1.f;
        wq[tid] = make_float4(w2[tid] * sg0, w2[72 + tid] * sg1,
                              w2[144 + tid] * sg2, w2[216 + tid] * sg3);
    }
    if (tid < 4) {
        float sgn = bn2g[tid] >= 0.f ? 1.f : -1.f;
        s_s2[tid] = sgn;
        bsh[tid] = b2[tid] * sgn;
    }
    if (tid < 8) sacc[tid] = 0.0;
    __syncthreads();

    float a1r[8], c1r[8];
#pragma unroll
    for (int ch = 0; ch < 8; ch++) { a1r[ch] = s_a1[ch]; c1r[ch] = s_c1[ch]; }

    // column-owner tile load: thread owns tile col c (<114), loops 10 rows
    for (int c = tid; c < 114; c += 224) {
        const int ww = c - 1;
        const bool cok = (ww >= 0) && (ww < 112);
#pragma unroll 2
        for (int r = 0; r < 10; r++) {
            int hh = h0 - 1 + r;
            float v[8];
            if (cok && hh >= 0 && hh < 112) {
                size_t base = (((size_t)n * 112 + hh) * 112 + ww) * 8;
                float4 x0 = *(const float4*)&g_h1[base];
                float4 x1 = *(const float4*)&g_h1[base + 4];
                float raw[8] = {x0.x, x0.y, x0.z, x0.w, x1.x, x1.y, x1.z, x1.w};
#pragma unroll
                for (int ch = 0; ch < 8; ch++)
                    v[ch] = fmaxf(fmaf(raw[ch], a1r[ch], c1r[ch]), 0.f);
            } else {
#pragma unroll
                for (int ch = 0; ch < 8; ch++) v[ch] = 0.f;
            }
#pragma unroll
            for (int ch = 0; ch < 8; ch++) tile[ch][r][c] = v[ch];
        }
    }
    __syncthreads();

    const int r = tid / 28, g = tid % 28;
    float y[4][4];  // [oc][px], accumulates y' = s2*y
    {
        float b0 = bsh[0], b1 = bsh[1], b2v = bsh[2], b3 = bsh[3];
#pragma unroll
        for (int p = 0; p < 4; p++) {
            y[0][p] = b0; y[1][p] = b1; y[2][p] = b2v; y[3][p] = b3;
        }
    }

#pragma unroll 1
    for (int ic = 0; ic < 8; ic++) {
#pragma unroll
        for (int kh = 0; kh < 3; kh++) {
            const float4 va = *(const float4*)&tile[ic][r + kh][4 * g];
            const float2 vb = *(const float2*)&tile[ic][r + kh][4 * g + 4];
            float t[6] = {va.x, va.y, va.z, va.w, vb.x, vb.y};
#pragma unroll
            for (int kw = 0; kw < 3; kw++) {
                float4 wv = wq[ic * 9 + kh * 3 + kw];
#pragma unroll
                for (int p = 0; p < 4; p++) {
                    float u = t[p + kw];
                    y[0][p] = fmaf(wv.x, u, y[0][p]);
                    y[1][p] = fmaf(wv.y, u, y[1][p]);
                    y[2][p] = fmaf(wv.z, u, y[2][p]);
                    y[3][p] = fmaf(wv.w, u, y[3][p]);
                }
            }
        }
    }

    // bn2 stats on true y (sum re-signed; sumsq sign-invariant)
#pragma unroll
    for (int j = 0; j < 4; j++) {
        float s = (y[j][0] + y[j][1]) + (y[j][2] + y[j][3]);
        float qq = fmaf(y[j][0], y[j][0], fmaf(y[j][1], y[j][1],
                   fmaf(y[j][2], y[j][2], y[j][3] * y[j][3])));
        float ws = warp_sum(s);
        float wq = warp_sum(qq);
        if ((tid & 31) == 0) {
            atomicAdd(&sacc[j], (double)(ws * s_s2[j]));
            atomicAdd(&sacc[4 + j], (double)wq);
        }
    }

    // stash y' into ybuf for in-block 2x2 max pooling
#pragma unroll
    for (int p = 0; p < 4; p++)
        ybuf[r][4 * g + p] = make_float4(y[0][p], y[1][p], y[2][p], y[3][p]);
    __syncthreads();

    // 224 threads = 4 pooled rows x 56 pooled cols, single plane out
    {
        const int ppr = tid / 56, ppw = tid % 56;
        float4 u0 = ybuf[2 * ppr][2 * ppw];
        float4 u1 = ybuf[2 * ppr][2 * ppw + 1];
        float4 u2 = ybuf[2 * ppr + 1][2 * ppw];
        float4 u3 = ybuf[2 * ppr + 1][2 * ppw + 1];
        float4 mx;
        mx.x = fmaxf(fmaxf(u0.x, u1.x), fmaxf(u2.x, u3.x));
        mx.y = fmaxf(fmaxf(u0.y, u1.y), fmaxf(u2.y, u3.y));
        mx.z = fmaxf(fmaxf(u0.z, u1.z), fmaxf(u2.z, u3.z));
        mx.w = fmaxf(fmaxf(u0.w, u1.w), fmaxf(u2.w, u3.w));
        size_t o = (((size_t)n * 56 + (blockIdx.x * 4 + ppr)) * 56 + ppw) * 4;
        *(float4*)&g_p2[o] = mx;
    }
    if (tid < 8) atomicAdd(&g_stats2[tid], sacc[tid]);
}

// ---------------------------------------------------------------------------
// Quantum circuit helpers.
template <int Q>
__device__ __forceinline__ void ry_gate(float2* st, float t) {
    float s, c;
    sincosf(0.5f * t, &s, &c);
    const int m = 8 >> Q;
#pragma unroll
    for (int i = 0; i < 16; i++)
        if (!(i & m)) {
            float2 a0 = st[i], a1 = st[i | m];
            st[i]     = make_float2(c * a0.x - s * a1.x, c * a0.y - s * a1.y);
            st[i | m] = make_float2(s * a0.x + c * a1.x, s * a0.y + c * a1.y);
        }
}
template <int Q>
__device__ __forceinline__ void rz_gate(float2* st, float t) {
    float s, c;
    sincosf(0.5f * t, &s, &c);
    const int m = 8 >> Q;
#pragma unroll
    for (int i = 0; i < 16; i++)
        if (!(i & m)) {
            float2 a0 = st[i], a1 = st[i | m];
            st[i]     = make_float2(c * a0.x + s * a0.y, c * a0.y - s * a0.x);
            st[i | m] = make_float2(c * a1.x - s * a1.y, c * a1.y + s * a1.x);
        }
}
template <int Q>
__device__ __forceinline__ void rx_gate(float2* st, float t) {
    float s, c;
    sincosf(0.5f * t, &s, &c);
    const int m = 8 >> Q;
#pragma unroll
    for (int i = 0; i < 16; i++)
        if (!(i & m)) {
            float2 a0 = st[i], a1 = st[i | m];
            st[i]     = make_float2(c * a0.x + s * a1.y, c * a0.y - s * a1.x);
            st[i | m] = make_float2(c * a1.x + s * a0.y, c * a1.y - s * a0.x);
        }
}
template <int C, int T>
__device__ __forceinline__ void cnot_gate(float2* st) {
    const int mc = 8 >> C, mt = 8 >> T;
#pragma unroll
    for (int i = 0; i < 16; i++)
        if ((i & mc) && !(i & mt)) {
            float2 tmp = st[i];
            st[i] = st[i | mt];
            st[i | mt] = tmp;
        }
}

// ---------------------------------------------------------------------------
// pool_mean + fused final: each block computes feat[n] from the single
// pooled plane (h2 = relu(|a2|*stored + c2)); last block runs standardize +
// circuit + output BN and resets state.  grid(128), block 256.
__global__ void k_pool_final(const float* __restrict__ bn2g,
                             const float* __restrict__ bn2b,
                             const float* __restrict__ theta,
                             const float* __restrict__ rho,
                             const float* __restrict__ ng,
                             const float* __restrict__ nb,
                             float* __restrict__ out) {
    __shared__ float s_a2[4], s_c2[4];
    __shared__ unsigned int s_last;
    const int n = blockIdx.x, tid = threadIdx.x;
    if (tid < 4) {
        double N = 128.0 * 112.0 * 112.0;
        double mu = g_stats2[tid] / N;
        double var = g_stats2[4 + tid] / N - mu * mu;
        double a = (double)bn2g[tid] * rsqrt(var + 1e-5);
        s_a2[tid] = fabsf((float)a);
        s_c2[tid] = (float)((double)bn2b[tid] - mu * a);
    }
    __syncthreads();
    const float4 av = *(const float4*)s_a2;
    const float4 cv = *(const float4*)s_c2;
    const float4* psel = (const float4*)&g_p2[(size_t)n * 56 * 56 * 4];
    float4 acc = make_float4(0.f, 0.f, 0.f, 0.f);

    for (int p = tid; p < 56 * 56; p += 256) {
        float4 mx = psel[p];
        acc.x += fmaxf(fmaf(mx.x, av.x, cv.x), 0.f);
        acc.y += fmaxf(fmaf(mx.y, av.y, cv.y), 0.f);
        acc.z += fmaxf(fmaf(mx.z, av.z, cv.z), 0.f);
        acc.w += fmaxf(fmaf(mx.w, av.w, cv.w), 0.f);
    }
    __shared__ float4 sm[8];
    acc.x = warp_sum(acc.x); acc.y = warp_sum(acc.y);
    acc.z = warp_sum(acc.z); acc.w = warp_sum(acc.w);
    if ((tid & 31) == 0) sm[tid >> 5] = acc;
    __syncthreads();
    if (tid == 0) {
        float4 t = make_float4(0.f, 0.f, 0.f, 0.f);
#pragma unroll
        for (int i = 0; i < 8; i++) {
            t.x += sm[i].x; t.y += sm[i].y; t.z += sm[i].z; t.w += sm[i].w;
        }
        *(float4*)&g_feat[n * 4] =
            make_float4(t.x / 3136.f, t.y / 3136.f, t.z / 3136.f, t.w / 3136.f);
        __threadfence();
        s_last = atomicAdd(&g_done, 1u);
    }
    __syncthreads();
    if (s_last != NB - 1) return;   // not the last block: done
    __threadfence();                // acquire: all g_feat writes visible

    // ---- fused final phase: threads 0..127 (one per batch element) ----
    if (tid == 0) {
        g_done = 0;                 // reset for graph replay
    }
    if (tid < 16) g_stats1[tid] = 0.0;
    if (tid < 8)  g_stats2[tid] = 0.0;
    if (tid >= 128) return;

    float f[4];
#pragma unroll
    for (int j = 0; j < 4; j++) f[j] = g_feat[tid * 4 + j];

    __shared__ double ssum, ssq;
    if (tid == 0) { ssum = 0.0; ssq = 0.0; }
    __syncthreads();
    float lf = f[0] + f[1] + f[2] + f[3];
    float lq = f[0] * f[0] + f[1] * f[1] + f[2] * f[2] + f[3] * f[3];
    float ws = warp_sum(lf), wq = warp_sum(lq);
    if ((tid & 31) == 0) { atomicAdd(&ssum, (double)ws); atomicAdd(&ssq, (double)wq); }
    __syncthreads();
    double mean = ssum / 512.0;
    double var1 = (ssq - 512.0 * mean * mean) / 511.0;
    if (var1 < 0.0) var1 = 0.0;
    float scale = (float)(3.14159265358979323846 / (sqrt(var1) + 1e-6));
    float sc[4];
#pragma unroll
    for (int j = 0; j < 4; j++) sc[j] = (float)((double)f[j] - mean) * scale;

    float2 st[16];
#pragma unroll
    for (int i = 0; i < 16; i++) st[i] = make_float2(0.f, 0.f);
    st[0].x = 1.f;

    ry_gate<0>(st, sc[0]); ry_gate<1>(st, sc[1]); ry_gate<2>(st, sc[2]); ry_gate<3>(st, sc[3]);

    ry_gate<0>(st, theta[0]);  rz_gate<0>(st, theta[1]);  rx_gate<0>(st, theta[2]);
    ry_gate<1>(st, theta[3]);  rz_gate<1>(st, theta[4]);  rx_gate<1>(st, theta[5]);
    ry_gate<2>(st, theta[6]);  rz_gate<2>(st, theta[7]);  rx_gate<2>(st, theta[8]);
    ry_gate<3>(st, theta[9]);  rz_gate<3>(st, theta[10]); rx_gate<3>(st, theta[11]);

    cnot_gate<0, 1>(st); cnot_gate<1, 2>(st); cnot_gate<2, 3>(st);

    ry_gate<0>(st, rho[0]);  rz_gate<0>(st, rho[1]);  rx_gate<0>(st, rho[2]);
    ry_gate<1>(st, rho[3]);  rz_gate<1>(st, rho[4]);  rx_gate<1>(st, rho[5]);
    ry_gate<2>(st, rho[6]);  rz_gate<2>(st, rho[7]);  rx_gate<2>(st, rho[8]);
    ry_gate<3>(st, rho[9]);  rz_gate<3>(st, rho[10]); rx_gate<3>(st, rho[11]);

    cnot_gate<1, 0>(st); cnot_gate<2, 1>(st); cnot_gate<3, 2>(st);

    float pr[16];
#pragma unroll
    for (int i = 0; i < 16; i++) pr[i] = st[i].x * st[i].x + st[i].y * st[i].y;

    float e[4];
#pragma unroll
    for (int q = 0; q < 4; q++) {
        const int m = 8 >> q;
        float a = 0.f;
#pragma unroll
        for (int i = 0; i < 16; i++) a += (i & m) ? -pr[i] : pr[i];
        e[q] = a;
    }

    __shared__ double s1, s2;
#pragma unroll
    for (int j = 0; j < 4; j++) {
        if (tid == 0) { s1 = 0.0; s2 = 0.0; }
        __syncthreads();
        float v = e[j];
        float w1 = warp_sum(v), w2 = warp_sum(v * v);
        if ((tid & 31) == 0) { atomicAdd(&s1, (double)w1); atomicAdd(&s2, (double)w2); }
        __syncthreads();
        double mu = s1 / 128.0;
        double vv = s2 / 128.0 - mu * mu;
        out[tid * 4 + j] =
            (float)(((double)v - mu) * rsqrt(vv + 1e-5) * (double)ng[j] + (double)nb[j]);
        __syncthreads();
    }
}

// ---------------------------------------------------------------------------
extern "C" void kernel_launch(void* const* d_in, const int* in_sizes, int n_in,
                              void* d_out, int out_size) {
    const float* x     = (const float*)d_in[0];
    const float* w1    = (const float*)d_in[1];
    const float* b1    = (const float*)d_in[2];
    const float* bn1g  = (const float*)d_in[3];
    const float* bn1b  = (const float*)d_in[4];
    const float* w2    = (const float*)d_in[5];
    const float* b2    = (const float*)d_in[6];
    const float* bn2g  = (const float*)d_in[7];
    const float* bn2b  = (const float*)d_in[8];
    const float* theta = (const float*)d_in[9];
    const float* rho   = (const float*)d_in[10];
    const float* ng    = (const float*)d_in[11];
    const float* nbp   = (const float*)d_in[12];
    float* out = (float*)d_out;

    k_conv1<<<dim3(14, NB), 224>>>(x, w1, b1, bn1g);
    k_conv2<<<dim3(14, NB), 224>>>(w2, b2, bn1g, bn1b, bn2g);
    k_pool_final<<<NB, 256>>>(bn2g, bn2b, theta, rho, ng, nbp, out);
}